// round 3
// baseline (speedup 1.0000x reference)
#include <cuda_runtime.h>

// CRF broadcast-add: out[b,l,i,j] = emission[b,l,j] + transition[i,j]
// B=32, L=512, T=64  ->  BL=16384 tiles, each tile = 64x64 fp32 = 4096 floats = 1024 float4
//
// Thread mapping (256 threads/block): thread t owns float4 positions
// p = t + 256k (k=0..3) within each tile. p%16 == t%16, so each thread
// needs ONE emission float4 per tile and its 4 transition float4s are
// tile-invariant -> kept in registers for the whole kernel.
//
// Store-bound kernel: 256 MB out, 4 MB in. Output lines are dead after the
// store -> evict-first streaming stores (__stcs) so L2 stays available for
// the emission stream.

constexpr int Bc = 32;
constexpr int Lc = 512;
constexpr int Tc = 64;
constexpr int BL = Bc * Lc;                 // 16384
constexpr int TILE_F4 = (Tc * Tc) / 4;      // 1024 float4 per tile
constexpr int EM_F4_PER_TILE = Tc / 4;      // 16 float4 emission per tile
constexpr int THREADS = 256;
constexpr int F4_PER_THREAD = TILE_F4 / THREADS;  // 4

__global__ void __launch_bounds__(THREADS, 8)
crf_broadcast_add(const float4* __restrict__ em4,
                  const float4* __restrict__ tr4,
                  float4* __restrict__ out4)
{
    const int t  = threadIdx.x;
    const int j4 = t & (EM_F4_PER_TILE - 1);   // t % 16

    // Transition rows this thread touches are fixed: load once into registers.
    float4 tr[F4_PER_THREAD];
#pragma unroll
    for (int k = 0; k < F4_PER_THREAD; ++k)
        tr[k] = __ldg(&tr4[t + THREADS * k]);

    for (int bl = blockIdx.x; bl < BL; bl += gridDim.x) {
        const float4 e = __ldg(&em4[(size_t)bl * EM_F4_PER_TILE + j4]);
        float4* __restrict__ o = out4 + (size_t)bl * TILE_F4;
#pragma unroll
        for (int k = 0; k < F4_PER_THREAD; ++k) {
            float4 v;
            v.x = e.x + tr[k].x;
            v.y = e.y + tr[k].y;
            v.z = e.z + tr[k].z;
            v.w = e.w + tr[k].w;
            __stcs(&o[t + THREADS * k], v);   // streaming: evict-first
        }
    }
}

extern "C" void kernel_launch(void* const* d_in, const int* in_sizes, int n_in,
                              void* d_out, int out_size)
{
    const float4* em4 = (const float4*)d_in[0];   // emission [B, L, T] fp32
    const float4* tr4 = (const float4*)d_in[1];   // transition [T, T] fp32
    float4* out4      = (float4*)d_out;           // [B, L, T, T] fp32

    // 8 CTAs per SM * 152 SMs (GB300) -> full occupancy, grid-stride over tiles.
    const int grid = 152 * 8;
    crf_broadcast_add<<<grid, THREADS>>>(em4, tr4, out4);
}